// round 1
// baseline (speedup 1.0000x reference)
#include <cuda_runtime.h>
#include <math.h>

#define S_LEN   2048
#define DIM     2048
#define NHEAD   16
#define HD      128
#define HIDDEN  5632
#define EPS     1e-6f

typedef unsigned long long u64;

// ---------------------------------------------------------------------------
// Scratch (device globals; allocation in kernel_launch is forbidden)
// ---------------------------------------------------------------------------
__device__ float g_xn[S_LEN * DIM];
__device__ float g_q [S_LEN * DIM];
__device__ float g_k [S_LEN * DIM];
__device__ float g_v [S_LEN * DIM];
__device__ float g_sc[NHEAD * S_LEN * S_LEN];   // 256 MB score matrix
__device__ float g_at[S_LEN * DIM];
__device__ float g_h [S_LEN * DIM];
__device__ float g_hn[S_LEN * DIM];
__device__ float g_u1[S_LEN * HIDDEN];          // silu(h@w1)*(h@w3)

// ---------------------------------------------------------------------------
// packed f32x2 helpers (sm_103a: doubles FFMA throughput vs scalar FFMA-3reg)
// ---------------------------------------------------------------------------
__device__ __forceinline__ u64 pack2(float x) {
    u64 r; asm("mov.b64 %0, {%1, %1};" : "=l"(r) : "f"(x)); return r;
}
__device__ __forceinline__ void fma2(u64 &d, u64 a, u64 b) {
    asm("fma.rn.f32x2 %0, %1, %2, %0;" : "+l"(d) : "l"(a), "l"(b));
}
__device__ __forceinline__ float2 unpack2(u64 v) {
    float2 f; asm("mov.b64 {%0, %1}, %2;" : "=f"(f.x), "=f"(f.y) : "l"(v)); return f;
}

// ---------------------------------------------------------------------------
// RMSNorm: one block per row
// ---------------------------------------------------------------------------
__global__ void rmsnorm_kernel(const float* __restrict__ x,
                               const float* __restrict__ g,
                               float* __restrict__ y) {
    const int row = blockIdx.x;
    const float* xr = x + (long long)row * DIM;
    float*       yr = y + (long long)row * DIM;

    float ss = 0.f;
    #pragma unroll
    for (int i = threadIdx.x; i < DIM / 4; i += 256) {
        float4 v = ((const float4*)xr)[i];
        ss += v.x * v.x + v.y * v.y + v.z * v.z + v.w * v.w;
    }
    __shared__ float red[8];
    #pragma unroll
    for (int o = 16; o; o >>= 1) ss += __shfl_xor_sync(0xffffffffu, ss, o);
    if ((threadIdx.x & 31) == 0) red[threadIdx.x >> 5] = ss;
    __syncthreads();
    __shared__ float rr_s;
    if (threadIdx.x == 0) {
        float v = 0.f;
        #pragma unroll
        for (int i = 0; i < 8; i++) v += red[i];
        rr_s = rsqrtf(v * (1.0f / DIM) + EPS);
    }
    __syncthreads();
    const float rr = rr_s;
    for (int i = threadIdx.x; i < DIM / 4; i += 256) {
        float4 v  = ((const float4*)xr)[i];
        float4 gg = ((const float4*)g)[i];
        v.x *= rr * gg.x; v.y *= rr * gg.y; v.z *= rr * gg.z; v.w *= rr * gg.w;
        ((float4*)yr)[i] = v;
    }
}

// ---------------------------------------------------------------------------
// RoPE applied in-place to q and k
// ---------------------------------------------------------------------------
__global__ void rope_kernel(float* __restrict__ q, float* __restrict__ k,
                            const float* __restrict__ fcos,
                            const float* __restrict__ fsin) {
    const int idx = blockIdx.x * blockDim.x + threadIdx.x;
    if (idx >= S_LEN * NHEAD * (HD / 2)) return;
    const int i = idx % (HD / 2);
    const int h = (idx / (HD / 2)) % NHEAD;
    const int s = idx / (NHEAD * (HD / 2));
    const float c  = fcos[s * (HD / 2) + i];
    const float sn = fsin[s * (HD / 2) + i];
    const long long off = (long long)s * DIM + h * HD + 2 * i;
    float qr = q[off], qi = q[off + 1];
    q[off]     = qr * c - qi * sn;
    q[off + 1] = qr * sn + qi * c;
    float kr = k[off], ki = k[off + 1];
    k[off]     = kr * c - ki * sn;
    k[off + 1] = kr * sn + ki * c;
}

// ---------------------------------------------------------------------------
// Causal softmax (in-place on the 256MB score buffer). One block per (s,h) row.
// Writes zeros for t > s so the PV GEMM can read whole 128-wide K tiles.
// ---------------------------------------------------------------------------
__global__ void softmax_causal(float* __restrict__ sc) {
    const int s = blockIdx.x, h = blockIdx.y;
    float* row = sc + ((long long)h * S_LEN + s) * S_LEN;
    const int L = s + 1;
    const float scale = 0.08838834764831845f;   // 1/sqrt(128)

    __shared__ float red[8];
    __shared__ float bmax, binv;

    float m = -1e30f;
    for (int t = threadIdx.x; t < L; t += 256) m = fmaxf(m, row[t]);
    #pragma unroll
    for (int o = 16; o; o >>= 1) m = fmaxf(m, __shfl_xor_sync(0xffffffffu, m, o));
    if ((threadIdx.x & 31) == 0) red[threadIdx.x >> 5] = m;
    __syncthreads();
    if (threadIdx.x == 0) {
        float v = red[0];
        #pragma unroll
        for (int i = 1; i < 8; i++) v = fmaxf(v, red[i]);
        bmax = v * scale;
    }
    __syncthreads();
    const float mm = bmax;

    float sum = 0.f;
    for (int t = threadIdx.x; t < L; t += 256) sum += expf(row[t] * scale - mm);
    #pragma unroll
    for (int o = 16; o; o >>= 1) sum += __shfl_xor_sync(0xffffffffu, sum, o);
    if ((threadIdx.x & 31) == 0) red[threadIdx.x >> 5] = sum;
    __syncthreads();
    if (threadIdx.x == 0) {
        float v = 0.f;
        #pragma unroll
        for (int i = 0; i < 8; i++) v += red[i];
        binv = 1.f / v;
    }
    __syncthreads();
    const float inv = binv;

    for (int t = threadIdx.x; t < S_LEN; t += 256)
        row[t] = (t < L) ? expf(row[t] * scale - mm) * inv : 0.f;
}

// ---------------------------------------------------------------------------
// Tiled SGEMM, fp32 in / fp32 out, packed f32x2 FMA inner loop.
//   C[M,N] = A[M,K] @ op(B) (+ epilogue)
// TRANS_B: 0 -> B is [K,N] row-major; 1 -> B is [N,K] row-major (C = A B^T)
// EPI: 0 none; 1 C = acc + D; 2 C = silu(D) * acc        (D has ld = ldc)
// CAUSAL: 0 none; 1 skip tiles with bx > by (scores); 2 K-loop ends at (by+1)*128 (PV)
// sA/sB/sC: per-blockIdx.z (head) element strides for batched attention GEMMs.
// Tile: 128x128x16, 256 threads, 8x8 per thread. All dims multiples of tiles.
// ---------------------------------------------------------------------------
template<int TRANS_B, int EPI, int CAUSAL>
__global__ __launch_bounds__(256, 2)
void sgemm(const float* __restrict__ A, const float* __restrict__ B,
           const float* __restrict__ D, float* __restrict__ C,
           int M, int N, int K, int lda, int ldb, int ldc,
           long long sA, long long sB, long long sC)
{
    const int bx = blockIdx.x, by = blockIdx.y, bz = blockIdx.z;
    if (CAUSAL == 1 && bx > by) return;          // fully-masked score tile
    A += (long long)bz * sA;
    B += (long long)bz * sB;
    C += (long long)bz * sC;

    const int m0 = by * 128, n0 = bx * 128;
    int kEnd = K;
    if (CAUSAL == 2) { int ke = (by + 1) * 128; kEnd = ke < K ? ke : K; }

    __shared__ float As[16][128];
    __shared__ float Bs[16][128];

    const int tid  = threadIdx.x;
    const int arow = tid >> 2;            // 0..63
    const int acol = (tid & 3) << 2;      // 0,4,8,12
    const int brow = tid >> 5;            // 0..7
    const int bcol = (tid & 31) << 2;     // 0..124
    const int tx = tid & 15, ty = tid >> 4;

    u64 acc[8][4];
    #pragma unroll
    for (int i = 0; i < 8; i++)
        #pragma unroll
        for (int j = 0; j < 4; j++) acc[i][j] = 0ull;

    for (int k0 = 0; k0 < kEnd; k0 += 16) {
        // A tile: 128 rows x 16 cols -> transposed into As[k][m]
        #pragma unroll
        for (int r = 0; r < 2; r++) {
            float4 v = *(const float4*)(A + (long long)(m0 + arow + r * 64) * lda + (k0 + acol));
            As[acol + 0][arow + r * 64] = v.x;
            As[acol + 1][arow + r * 64] = v.y;
            As[acol + 2][arow + r * 64] = v.z;
            As[acol + 3][arow + r * 64] = v.w;
        }
        if (TRANS_B) {
            // B is [N,K]: load like A, transpose into Bs[k][n]
            #pragma unroll
            for (int r = 0; r < 2; r++) {
                float4 v = *(const float4*)(B + (long long)(n0 + arow + r * 64) * ldb + (k0 + acol));
                Bs[acol + 0][arow + r * 64] = v.x;
                Bs[acol + 1][arow + r * 64] = v.y;
                Bs[acol + 2][arow + r * 64] = v.z;
                Bs[acol + 3][arow + r * 64] = v.w;
            }
        } else {
            // B is [K,N]: straight copy
            #pragma unroll
            for (int r = 0; r < 2; r++) {
                float4 v = *(const float4*)(B + (long long)(k0 + brow + r * 8) * ldb + (n0 + bcol));
                *(float4*)&Bs[brow + r * 8][bcol] = v;
            }
        }
        __syncthreads();

        #pragma unroll
        for (int kk = 0; kk < 16; kk++) {
            float4 a0 = *(const float4*)&As[kk][ty * 4];
            float4 a1 = *(const float4*)&As[kk][64 + ty * 4];
            ulonglong2 b0 = *(const ulonglong2*)&Bs[kk][tx * 4];
            ulonglong2 b1 = *(const ulonglong2*)&Bs[kk][64 + tx * 4];
            u64 ap[8];
            ap[0] = pack2(a0.x); ap[1] = pack2(a0.y); ap[2] = pack2(a0.z); ap[3] = pack2(a0.w);
            ap[4] = pack2(a1.x); ap[5] = pack2(a1.y); ap[6] = pack2(a1.z); ap[7] = pack2(a1.w);
            #pragma unroll
            for (int i = 0; i < 8; i++) {
                fma2(acc[i][0], ap[i], b0.x);
                fma2(acc[i][1], ap[i], b0.y);
                fma2(acc[i][2], ap[i], b1.x);
                fma2(acc[i][3], ap[i], b1.y);
            }
        }
        __syncthreads();
    }

    #pragma unroll
    for (int i = 0; i < 8; i++) {
        const int m = m0 + ty * 4 + ((i >> 2) << 6) + (i & 3);
        float* crow = C + (long long)m * ldc + n0;
        const float* drow = (EPI != 0) ? (D + (long long)m * ldc + n0) : nullptr;
        #pragma unroll
        for (int jj = 0; jj < 2; jj++) {
            const int nb = tx * 4 + jj * 64;
            float2 lo = unpack2(acc[i][jj * 2 + 0]);
            float2 hi = unpack2(acc[i][jj * 2 + 1]);
            float4 v = make_float4(lo.x, lo.y, hi.x, hi.y);
            if (EPI == 1) {
                float4 d = *(const float4*)(drow + nb);
                v.x += d.x; v.y += d.y; v.z += d.z; v.w += d.w;
            } else if (EPI == 2) {
                float4 d = *(const float4*)(drow + nb);
                v.x *= d.x / (1.f + expf(-d.x));
                v.y *= d.y / (1.f + expf(-d.y));
                v.z *= d.z / (1.f + expf(-d.z));
                v.w *= d.w / (1.f + expf(-d.w));
            }
            *(float4*)(crow + nb) = v;
        }
    }
}

// ---------------------------------------------------------------------------
// Orchestration
// ---------------------------------------------------------------------------
extern "C" void kernel_launch(void* const* d_in, const int* in_sizes, int n_in,
                              void* d_out, int out_size) {
    const float* x  = (const float*)d_in[0];
    const float* fc = (const float*)d_in[1];
    const float* fs = (const float*)d_in[2];
    // d_in[3] = mask (causal, known statically -> unused)
    const float* wq = (const float*)d_in[4];
    const float* wk = (const float*)d_in[5];
    const float* wv = (const float*)d_in[6];
    const float* wo = (const float*)d_in[7];
    const float* w1 = (const float*)d_in[8];
    const float* w2 = (const float*)d_in[9];
    const float* w3 = (const float*)d_in[10];
    const float* ga = (const float*)d_in[11];
    const float* gf = (const float*)d_in[12];
    float* out = (float*)d_out;

    float *xn, *q, *k, *v, *sc, *at, *h, *hn, *u1;
    cudaGetSymbolAddress((void**)&xn, g_xn);
    cudaGetSymbolAddress((void**)&q,  g_q);
    cudaGetSymbolAddress((void**)&k,  g_k);
    cudaGetSymbolAddress((void**)&v,  g_v);
    cudaGetSymbolAddress((void**)&sc, g_sc);
    cudaGetSymbolAddress((void**)&at, g_at);
    cudaGetSymbolAddress((void**)&h,  g_h);
    cudaGetSymbolAddress((void**)&hn, g_hn);
    cudaGetSymbolAddress((void**)&u1, g_u1);

    const dim3 g16(16, 16, 1);

    // 1) xn = rmsnorm(x, g_attn)
    rmsnorm_kernel<<<S_LEN, 256>>>(x, ga, xn);

    // 2) q/k/v = xn @ wq/wk/wv
    sgemm<0, 0, 0><<<g16, 256>>>(xn, wq, nullptr, q, S_LEN, DIM, DIM, DIM, DIM, DIM, 0, 0, 0);
    sgemm<0, 0, 0><<<g16, 256>>>(xn, wk, nullptr, k, S_LEN, DIM, DIM, DIM, DIM, DIM, 0, 0, 0);
    sgemm<0, 0, 0><<<g16, 256>>>(xn, wv, nullptr, v, S_LEN, DIM, DIM, DIM, DIM, DIM, 0, 0, 0);

    // 3) RoPE on q, k
    rope_kernel<<<(S_LEN * NHEAD * (HD / 2) + 255) / 256, 256>>>(q, k, fc, fs);

    // 4) scores[h] = Q_h @ K_h^T  (causal tiles skipped)
    sgemm<1, 0, 1><<<dim3(16, 16, NHEAD), 256>>>(q, k, nullptr, sc,
        S_LEN, S_LEN, HD, DIM, DIM, S_LEN, HD, HD, (long long)S_LEN * S_LEN);

    // 5) softmax (scale + causal mask), zero-fills t > s
    softmax_causal<<<dim3(S_LEN, NHEAD), 256>>>(sc);

    // 6) attn[h] = P_h @ V_h  (K-loop truncated at causal boundary)
    sgemm<0, 0, 2><<<dim3(1, 16, NHEAD), 256>>>(sc, v, nullptr, at,
        S_LEN, HD, S_LEN, S_LEN, DIM, DIM, (long long)S_LEN * S_LEN, HD, HD);

    // 7) h = x + attn @ wo
    sgemm<0, 1, 0><<<g16, 256>>>(at, wo, x, h, S_LEN, DIM, DIM, DIM, DIM, DIM, 0, 0, 0);

    // 8) hn = rmsnorm(h, g_ffn)
    rmsnorm_kernel<<<S_LEN, 256>>>(h, gf, hn);

    // 9) u1 = hn @ w1 ; u1 = silu(u1) * (hn @ w3)
    sgemm<0, 0, 0><<<dim3(44, 16, 1), 256>>>(hn, w1, nullptr, u1,
        S_LEN, HIDDEN, DIM, DIM, HIDDEN, HIDDEN, 0, 0, 0);
    sgemm<0, 2, 0><<<dim3(44, 16, 1), 256>>>(hn, w3, u1, u1,
        S_LEN, HIDDEN, DIM, DIM, HIDDEN, HIDDEN, 0, 0, 0);

    // 10) out = h + u1 @ w2
    sgemm<0, 1, 0><<<g16, 256>>>(u1, w2, h, out, S_LEN, DIM, HIDDEN, HIDDEN, DIM, DIM, 0, 0, 0);
}

// round 3
// speedup vs baseline: 2.1628x; 2.1628x over previous
#include <cuda_runtime.h>
#include <cuda_bf16.h>
#include <math.h>
#include <stdint.h>

#define S_LEN   2048
#define DIM     2048
#define NHEAD   16
#define HD      128
#define HIDDEN  5632
#define EPS     1e-6f

using bf16 = __nv_bfloat16;

// ---------------------------------------------------------------------------
// Device scratch (no runtime allocation allowed)
// ---------------------------------------------------------------------------
__device__ float g_sc [(size_t)NHEAD * S_LEN * S_LEN];     // fp32 scores
__device__ float g_qf [S_LEN * DIM];
__device__ float g_kf [S_LEN * DIM];
__device__ float g_vf [S_LEN * DIM];
__device__ float g_h  [S_LEN * DIM];
__device__ float g_u1a[(size_t)S_LEN * HIDDEN];

__device__ bf16 g_xn_h[S_LEN * DIM],  g_xn_l[S_LEN * DIM];
__device__ bf16 g_q_h [S_LEN * DIM],  g_q_l [S_LEN * DIM];
__device__ bf16 g_k_h [S_LEN * DIM],  g_k_l [S_LEN * DIM];
__device__ bf16 g_vT_h[NHEAD * HD * S_LEN], g_vT_l[NHEAD * HD * S_LEN];
__device__ bf16 g_p_h [(size_t)NHEAD * S_LEN * S_LEN];
__device__ bf16 g_p_l [(size_t)NHEAD * S_LEN * S_LEN];
__device__ bf16 g_at_h[S_LEN * DIM],  g_at_l[S_LEN * DIM];
__device__ bf16 g_hn_h[S_LEN * DIM],  g_hn_l[S_LEN * DIM];
__device__ bf16 g_u1_h[(size_t)S_LEN * HIDDEN], g_u1_l[(size_t)S_LEN * HIDDEN];

__device__ bf16 g_wqT_h[DIM * DIM], g_wqT_l[DIM * DIM];
__device__ bf16 g_wkT_h[DIM * DIM], g_wkT_l[DIM * DIM];
__device__ bf16 g_wvT_h[DIM * DIM], g_wvT_l[DIM * DIM];
__device__ bf16 g_woT_h[DIM * DIM], g_woT_l[DIM * DIM];
__device__ bf16 g_w1T_h[(size_t)HIDDEN * DIM], g_w1T_l[(size_t)HIDDEN * DIM];
__device__ bf16 g_w3T_h[(size_t)HIDDEN * DIM], g_w3T_l[(size_t)HIDDEN * DIM];
__device__ bf16 g_w2T_h[(size_t)DIM * HIDDEN], g_w2T_l[(size_t)DIM * HIDDEN];

// ---------------------------------------------------------------------------
// Helpers
// ---------------------------------------------------------------------------
__device__ __forceinline__ uint32_t smem_u32(const void* p) {
    uint32_t a;
    asm("{ .reg .u64 t; cvta.to.shared.u64 t, %1; cvt.u32.u64 %0, t; }" : "=r"(a) : "l"(p));
    return a;
}
__device__ __forceinline__ void cpa16(uint32_t d, const void* g) {
    asm volatile("cp.async.cg.shared.global [%0], [%1], 16;" :: "r"(d), "l"(g));
}
__device__ __forceinline__ void ldm_x4(uint32_t a, uint32_t (&f)[4]) {
    asm volatile("ldmatrix.sync.aligned.m8n8.x4.shared.b16 {%0,%1,%2,%3}, [%4];"
                 : "=r"(f[0]), "=r"(f[1]), "=r"(f[2]), "=r"(f[3]) : "r"(a));
}
__device__ __forceinline__ void mma16816(float (&c)[4], const uint32_t (&a)[4],
                                         uint32_t b0, uint32_t b1) {
    asm volatile("mma.sync.aligned.m16n8k16.row.col.f32.bf16.bf16.f32 "
                 "{%0,%1,%2,%3}, {%4,%5,%6,%7}, {%8,%9}, {%0,%1,%2,%3};"
                 : "+f"(c[0]), "+f"(c[1]), "+f"(c[2]), "+f"(c[3])
                 : "r"(a[0]), "r"(a[1]), "r"(a[2]), "r"(a[3]), "r"(b0), "r"(b1));
}
__device__ __forceinline__ void split2(float v, bf16& h, bf16& l) {
    h = __float2bfloat16(v);
    l = __float2bfloat16(v - __bfloat162float(h));
}

// swizzled byte offset within a 128x32-bf16 tile (64B rows, 16B segs)
__device__ __forceinline__ uint32_t swz(int row, int seg) {
    return (uint32_t)(row * 64 + ((seg ^ ((row >> 1) & 3)) << 4));
}

// stage a 128x32 bf16 tile smem<-gmem via cp.async (256 threads)
__device__ __forceinline__ void load_tile(const bf16* __restrict__ src, int ld,
                                          uint32_t dst, int tid) {
#pragma unroll
    for (int i = 0; i < 2; i++) {
        const int s = tid + i * 256;        // 0..511
        const int row = s >> 2, seg = s & 3;
        cpa16(dst + swz(row, seg), src + (size_t)row * ld + seg * 8);
    }
}

// ---------------------------------------------------------------------------
// mma_gemm: C[M,N] = (Ah+Al)[M,K] @ (Bh+Bl)[N,K]^T via mma.sync bf16 3-term
// EPI: 0 fp32; 1 fp32 + Dx; 2 split(silu(Dx)*acc); 3 split(acc)
// CAUSAL: 0 none; 1 skip bx>by; 2 K-loop ends at (by+1)*128
// 128x128 tile, 8 warps (2x4), warp 64x32, K-chunk 32, 2-stage cp.async.
// ---------------------------------------------------------------------------
#define GEMM_SMEM 65536

template<int EPI, int CAUSAL>
__global__ __launch_bounds__(256)
void mma_gemm(const bf16* __restrict__ Ah_, const bf16* __restrict__ Al_, int lda, long long zA,
              const bf16* __restrict__ Bh_, const bf16* __restrict__ Bl_, int ldb, long long zB,
              float* __restrict__ Cf, const float* __restrict__ Dx,
              bf16* __restrict__ Ch, bf16* __restrict__ Cl, int ldc, long long zC, int K)
{
    const int bx = blockIdx.x, by = blockIdx.y, z = blockIdx.z;
    if (CAUSAL == 1 && bx > by) return;
    const int m0 = by * 128, n0 = bx * 128;
    int kEnd = K;
    if (CAUSAL == 2) { int ke = (by + 1) * 128; kEnd = ke < K ? ke : K; }
    const int nc = kEnd >> 5;

    extern __shared__ char smem[];
    const uint32_t sb = smem_u32(smem);
    const int tid = threadIdx.x, wid = tid >> 5, lid = tid & 31;
    const int wm = wid >> 2, wn = wid & 3;

    const bf16* pAh = Ah_ + (size_t)z * zA + (size_t)m0 * lda;
    const bf16* pAl = Al_ + (size_t)z * zA + (size_t)m0 * lda;
    const bf16* pBh = Bh_ + (size_t)z * zB + (size_t)n0 * ldb;
    const bf16* pBl = Bl_ + (size_t)z * zB + (size_t)n0 * ldb;

    float acc[4][4][4];
#pragma unroll
    for (int i = 0; i < 4; i++)
#pragma unroll
        for (int j = 0; j < 4; j++)
#pragma unroll
            for (int t = 0; t < 4; t++) acc[i][j][t] = 0.f;

    // prologue: chunk 0
    {
        const uint32_t base = sb;
        load_tile(pAh, lda, base,         tid);
        load_tile(pAl, lda, base + 8192,  tid);
        load_tile(pBh, ldb, base + 16384, tid);
        load_tile(pBl, ldb, base + 24576, tid);
        asm volatile("cp.async.commit_group;" ::: "memory");
    }

    const int quad = lid >> 3, rr = lid & 7;

    for (int c = 0; c < nc; c++) {
        if (c + 1 < nc) {
            const uint32_t base = sb + ((c + 1) & 1) * 32768;
            const int k0 = (c + 1) * 32;
            load_tile(pAh + k0, lda, base,         tid);
            load_tile(pAl + k0, lda, base + 8192,  tid);
            load_tile(pBh + k0, ldb, base + 16384, tid);
            load_tile(pBl + k0, ldb, base + 24576, tid);
        }
        asm volatile("cp.async.commit_group;" ::: "memory");
        asm volatile("cp.async.wait_group 1;" ::: "memory");
        __syncthreads();

        const uint32_t base = sb + (c & 1) * 32768;
#pragma unroll
        for (int ks = 0; ks < 2; ks++) {
            uint32_t AhF[4][4], AlF[4][4], BhF[2][4], BlF[2][4];
#pragma unroll
            for (int mi = 0; mi < 4; mi++) {
                const int row = wm * 64 + mi * 16 + ((quad & 1) << 3) + rr;
                const int seg = ks * 2 + (quad >> 1);
                const uint32_t a = base + swz(row, seg);
                ldm_x4(a,        AhF[mi]);
                ldm_x4(a + 8192, AlF[mi]);
            }
#pragma unroll
            for (int nj = 0; nj < 2; nj++) {
                const int row = wn * 32 + nj * 16 + ((quad >> 1) << 3) + rr;
                const int seg = ks * 2 + (quad & 1);
                const uint32_t a = base + 16384 + swz(row, seg);
                ldm_x4(a,        BhF[nj]);
                ldm_x4(a + 8192, BlF[nj]);
            }
            // pass 1: Ah * Bh
#pragma unroll
            for (int mi = 0; mi < 4; mi++)
#pragma unroll
                for (int nj = 0; nj < 2; nj++) {
                    mma16816(acc[mi][nj * 2],     AhF[mi], BhF[nj][0], BhF[nj][1]);
                    mma16816(acc[mi][nj * 2 + 1], AhF[mi], BhF[nj][2], BhF[nj][3]);
                }
            // pass 2: Ah * Bl
#pragma unroll
            for (int mi = 0; mi < 4; mi++)
#pragma unroll
                for (int nj = 0; nj < 2; nj++) {
                    mma16816(acc[mi][nj * 2],     AhF[mi], BlF[nj][0], BlF[nj][1]);
                    mma16816(acc[mi][nj * 2 + 1], AhF[mi], BlF[nj][2], BlF[nj][3]);
                }
            // pass 3: Al * Bh
#pragma unroll
            for (int mi = 0; mi < 4; mi++)
#pragma unroll
                for (int nj = 0; nj < 2; nj++) {
                    mma16816(acc[mi][nj * 2],     AlF[mi], BhF[nj][0], BhF[nj][1]);
                    mma16816(acc[mi][nj * 2 + 1], AlF[mi], BhF[nj][2], BhF[nj][3]);
                }
        }
        __syncthreads();
    }

    // epilogue (direct from registers)
    const int gid = lid >> 2, tig = lid & 3;
    if (Cf) Cf += (size_t)z * zC;
    if (Ch) Ch += (size_t)z * zC;
    if (Cl) Cl += (size_t)z * zC;

#pragma unroll
    for (int mi = 0; mi < 4; mi++) {
#pragma unroll
        for (int k4 = 0; k4 < 4; k4++) {
            const int col = n0 + wn * 32 + k4 * 8 + tig * 2;
#pragma unroll
            for (int h2 = 0; h2 < 2; h2++) {
                const int row = m0 + wm * 64 + mi * 16 + gid + h2 * 8;
                float v0 = acc[mi][k4][h2 * 2 + 0];
                float v1 = acc[mi][k4][h2 * 2 + 1];
                const size_t off = (size_t)row * ldc + col;
                if (EPI == 0) {
                    *(float2*)(Cf + off) = make_float2(v0, v1);
                } else if (EPI == 1) {
                    float2 d = *(const float2*)(Dx + off);
                    *(float2*)(Cf + off) = make_float2(v0 + d.x, v1 + d.y);
                } else {
                    if (EPI == 2) {
                        float2 d = *(const float2*)(Dx + off);
                        v0 *= d.x / (1.f + expf(-d.x));
                        v1 *= d.y / (1.f + expf(-d.y));
                    }
                    bf16 h0, l0, h1, l1;
                    split2(v0, h0, l0); split2(v1, h1, l1);
                    __nv_bfloat162 t;
                    t.x = h0; t.y = h1; *(__nv_bfloat162*)(Ch + off) = t;
                    t.x = l0; t.y = l1; *(__nv_bfloat162*)(Cl + off) = t;
                }
            }
        }
    }
}

// ---------------------------------------------------------------------------
// RMSNorm -> split bf16 hi/lo
// ---------------------------------------------------------------------------
__global__ void rmsnorm_split_kernel(const float* __restrict__ x, const float* __restrict__ g,
                                     bf16* __restrict__ yh, bf16* __restrict__ yl) {
    const int row = blockIdx.x;
    const float* xr = x + (size_t)row * DIM;
    float ss = 0.f;
    for (int i = threadIdx.x; i < DIM / 4; i += 256) {
        float4 v = ((const float4*)xr)[i];
        ss += v.x * v.x + v.y * v.y + v.z * v.z + v.w * v.w;
    }
    __shared__ float red[8];
    __shared__ float rr_s;
#pragma unroll
    for (int o = 16; o; o >>= 1) ss += __shfl_xor_sync(0xffffffffu, ss, o);
    if ((threadIdx.x & 31) == 0) red[threadIdx.x >> 5] = ss;
    __syncthreads();
    if (threadIdx.x == 0) {
        float v = 0.f;
#pragma unroll
        for (int i = 0; i < 8; i++) v += red[i];
        rr_s = rsqrtf(v * (1.0f / DIM) + EPS);
    }
    __syncthreads();
    const float rr = rr_s;
    for (int i = threadIdx.x; i < DIM / 4; i += 256) {
        float4 v  = ((const float4*)xr)[i];
        float4 gg = ((const float4*)g)[i];
        v.x *= rr * gg.x; v.y *= rr * gg.y; v.z *= rr * gg.z; v.w *= rr * gg.w;
        bf16 h0, l0, h1, l1, h2, l2, h3, l3;
        split2(v.x, h0, l0); split2(v.y, h1, l1); split2(v.z, h2, l2); split2(v.w, h3, l3);
        const size_t o = (size_t)row * DIM + i * 4;
        __nv_bfloat162 a, b;
        a.x = h0; a.y = h1; b.x = h2; b.y = h3;
        *(__nv_bfloat162*)(yh + o) = a; *(__nv_bfloat162*)(yh + o + 2) = b;
        a.x = l0; a.y = l1; b.x = l2; b.y = l3;
        *(__nv_bfloat162*)(yl + o) = a; *(__nv_bfloat162*)(yl + o + 2) = b;
    }
}

// ---------------------------------------------------------------------------
// Weight transpose + split: W[K,N] -> WT_hi/lo[N,K]
// ---------------------------------------------------------------------------
__global__ void wsplitT_kernel(const float* __restrict__ W, int K, int N,
                               bf16* __restrict__ Th, bf16* __restrict__ Tl) {
    __shared__ float tb[32][33];
    const int n0 = blockIdx.x * 32, k0 = blockIdx.y * 32;
    const int tx = threadIdx.x, ty = threadIdx.y;
#pragma unroll
    for (int r = 0; r < 4; r++)
        tb[ty + 8 * r][tx] = W[(size_t)(k0 + ty + 8 * r) * N + n0 + tx];
    __syncthreads();
#pragma unroll
    for (int r = 0; r < 4; r++) {
        float v = tb[tx][ty + 8 * r];
        bf16 h, l; split2(v, h, l);
        const size_t o = (size_t)(n0 + ty + 8 * r) * K + k0 + tx;
        Th[o] = h; Tl[o] = l;
    }
}

// V transpose per head + split: v[S,DIM] -> vT[h][d][t]
__global__ void vsplitT_kernel(const float* __restrict__ vf,
                               bf16* __restrict__ Th, bf16* __restrict__ Tl) {
    __shared__ float tb[32][33];
    const int t0 = blockIdx.x * 32, d0 = blockIdx.y * 32, h = blockIdx.z;
    const int tx = threadIdx.x, ty = threadIdx.y;
#pragma unroll
    for (int r = 0; r < 4; r++)
        tb[ty + 8 * r][tx] = vf[(size_t)(t0 + ty + 8 * r) * DIM + h * HD + d0 + tx];
    __syncthreads();
#pragma unroll
    for (int r = 0; r < 4; r++) {
        float v = tb[tx][ty + 8 * r];
        bf16 hh, ll; split2(v, hh, ll);
        const size_t o = ((size_t)h * HD + d0 + ty + 8 * r) * S_LEN + t0 + tx;
        Th[o] = hh; Tl[o] = ll;
    }
}

// ---------------------------------------------------------------------------
// RoPE on fp32 q,k -> split bf16 hi/lo
// ---------------------------------------------------------------------------
__global__ void rope_split_kernel(const float* __restrict__ qf, const float* __restrict__ kf,
                                  const float* __restrict__ fc, const float* __restrict__ fs,
                                  bf16* __restrict__ qh, bf16* __restrict__ ql,
                                  bf16* __restrict__ kh, bf16* __restrict__ kl) {
    const int idx = blockIdx.x * blockDim.x + threadIdx.x;
    if (idx >= S_LEN * NHEAD * (HD / 2)) return;
    const int i = idx & 63;
    const int h = (idx >> 6) & 15;
    const int s = idx >> 10;
    const float c  = fc[s * 64 + i];
    const float sn = fs[s * 64 + i];
    const size_t off = (size_t)s * DIM + h * HD + 2 * i;

    {
        float qr = qf[off], qi = qf[off + 1];
        float a = qr * c - qi * sn, b = qr * sn + qi * c;
        bf16 ha, la, hb, lb; split2(a, ha, la); split2(b, hb, lb);
        __nv_bfloat162 t;
        t.x = ha; t.y = hb; *(__nv_bfloat162*)(qh + off) = t;
        t.x = la; t.y = lb; *(__nv_bfloat162*)(ql + off) = t;
    }
    {
        float kr = kf[off], ki = kf[off + 1];
        float a = kr * c - ki * sn, b = kr * sn + ki * c;
        bf16 ha, la, hb, lb; split2(a, ha, la); split2(b, hb, lb);
        __nv_bfloat162 t;
        t.x = ha; t.y = hb; *(__nv_bfloat162*)(kh + off) = t;
        t.x = la; t.y = lb; *(__nv_bfloat162*)(kl + off) = t;
    }
}

// ---------------------------------------------------------------------------
// Causal softmax on fp32 scores -> split bf16 probs (zeros for t > s)
// ---------------------------------------------------------------------------
__global__ void softmax_split_kernel(const float* __restrict__ sc,
                                     bf16* __restrict__ ph, bf16* __restrict__ pl) {
    const int s = blockIdx.x, h = blockIdx.y;
    const float* row = sc + ((size_t)h * S_LEN + s) * S_LEN;
    bf16* oh = ph + ((size_t)h * S_LEN + s) * S_LEN;
    bf16* ol = pl + ((size_t)h * S_LEN + s) * S_LEN;
    const int L = s + 1;
    const float scale = 0.08838834764831845f;

    __shared__ float red[8];
    __shared__ float bmax, binv;

    float m = -1e30f;
    for (int t = threadIdx.x; t < L; t += 256) m = fmaxf(m, row[t]);
#pragma unroll
    for (int o = 16; o; o >>= 1) m = fmaxf(m, __shfl_xor_sync(0xffffffffu, m, o));
    if ((threadIdx.x & 31) == 0) red[threadIdx.x >> 5] = m;
    __syncthreads();
    if (threadIdx.x == 0) {
        float v = red[0];
#pragma unroll
        for (int i = 1; i < 8; i++) v = fmaxf(v, red[i]);
        bmax = v * scale;
    }
    __syncthreads();
    const float mm = bmax;

    float sum = 0.f;
    for (int t = threadIdx.x; t < L; t += 256) sum += expf(row[t] * scale - mm);
#pragma unroll
    for (int o = 16; o; o >>= 1) sum += __shfl_xor_sync(0xffffffffu, sum, o);
    if ((threadIdx.x & 31) == 0) red[threadIdx.x >> 5] = sum;
    __syncthreads();
    if (threadIdx.x == 0) {
        float v = 0.f;
#pragma unroll
        for (int i = 0; i < 8; i++) v += red[i];
        binv = 1.f / v;
    }
    __syncthreads();
    const float inv = binv;

    for (int t = threadIdx.x; t < S_LEN; t += 256) {
        float e = (t < L) ? expf(row[t] * scale - mm) * inv : 0.f;
        bf16 hh, ll; split2(e, hh, ll);
        oh[t] = hh; ol[t] = ll;
    }
}

// ---------------------------------------------------------------------------
// Orchestration
// ---------------------------------------------------------------------------
extern "C" void kernel_launch(void* const* d_in, const int* in_sizes, int n_in,
                              void* d_out, int out_size) {
    const float* x  = (const float*)d_in[0];
    const float* fc = (const float*)d_in[1];
    const float* fs = (const float*)d_in[2];
    const float* wq = (const float*)d_in[4];
    const float* wk = (const float*)d_in[5];
    const float* wv = (const float*)d_in[6];
    const float* wo = (const float*)d_in[7];
    const float* w1 = (const float*)d_in[8];
    const float* w2 = (const float*)d_in[9];
    const float* w3 = (const float*)d_in[10];
    const float* ga = (const float*)d_in[11];
    const float* gf = (const float*)d_in[12];
    float* out = (float*)d_out;

    cudaFuncSetAttribute(mma_gemm<0, 0>, cudaFuncAttributeMaxDynamicSharedMemorySize, GEMM_SMEM);
    cudaFuncSetAttribute(mma_gemm<0, 1>, cudaFuncAttributeMaxDynamicSharedMemorySize, GEMM_SMEM);
    cudaFuncSetAttribute(mma_gemm<3, 2>, cudaFuncAttributeMaxDynamicSharedMemorySize, GEMM_SMEM);
    cudaFuncSetAttribute(mma_gemm<1, 0>, cudaFuncAttributeMaxDynamicSharedMemorySize, GEMM_SMEM);
    cudaFuncSetAttribute(mma_gemm<2, 0>, cudaFuncAttributeMaxDynamicSharedMemorySize, GEMM_SMEM);

    float *sc, *qf, *kf, *vf, *h, *u1a;
    bf16 *xnh, *xnl, *qh, *ql, *kh, *kl, *vTh, *vTl, *pph, *ppl, *ath, *atl, *hnh, *hnl, *u1h, *u1l;
    bf16 *wqh, *wql, *wkh, *wkl, *wvh, *wvl, *woh, *wol, *w1h, *w1l, *w2h, *w2l, *w3h, *w3l;
    cudaGetSymbolAddress((void**)&sc,  g_sc);
    cudaGetSymbolAddress((void**)&qf,  g_qf);
    cudaGetSymbolAddress((void**)&kf,  g_kf);
    cudaGetSymbolAddress((void**)&vf,  g_vf);
    cudaGetSymbolAddress((void**)&h,   g_h);
    cudaGetSymbolAddress((void**)&u1a, g_u1a);
    cudaGetSymbolAddress((void**)&xnh, g_xn_h); cudaGetSymbolAddress((void**)&xnl, g_xn_l);
    cudaGetSymbolAddress((void**)&qh,  g_q_h);  cudaGetSymbolAddress((void**)&ql,  g_q_l);
    cudaGetSymbolAddress((void**)&kh,  g_k_h);  cudaGetSymbolAddress((void**)&kl,  g_k_l);
    cudaGetSymbolAddress((void**)&vTh, g_vT_h); cudaGetSymbolAddress((void**)&vTl, g_vT_l);
    cudaGetSymbolAddress((void**)&pph, g_p_h);  cudaGetSymbolAddress((void**)&ppl, g_p_l);
    cudaGetSymbolAddress((void**)&ath, g_at_h); cudaGetSymbolAddress((void**)&atl, g_at_l);
    cudaGetSymbolAddress((void**)&hnh, g_hn_h); cudaGetSymbolAddress((void**)&hnl, g_hn_l);
    cudaGetSymbolAddress((void**)&u1h, g_u1_h); cudaGetSymbolAddress((void**)&u1l, g_u1_l);
    cudaGetSymbolAddress((void**)&wqh, g_wqT_h); cudaGetSymbolAddress((void**)&wql, g_wqT_l);
    cudaGetSymbolAddress((void**)&wkh, g_wkT_h); cudaGetSymbolAddress((void**)&wkl, g_wkT_l);
    cudaGetSymbolAddress((void**)&wvh, g_wvT_h); cudaGetSymbolAddress((void**)&wvl, g_wvT_l);
    cudaGetSymbolAddress((void**)&woh, g_woT_h); cudaGetSymbolAddress((void**)&wol, g_woT_l);
    cudaGetSymbolAddress((void**)&w1h, g_w1T_h); cudaGetSymbolAddress((void**)&w1l, g_w1T_l);
    cudaGetSymbolAddress((void**)&w2h, g_w2T_h); cudaGetSymbolAddress((void**)&w2l, g_w2T_l);
    cudaGetSymbolAddress((void**)&w3h, g_w3T_h); cudaGetSymbolAddress((void**)&w3l, g_w3T_l);

    const dim3 tb32(32, 8);

    // Weight transpose + split
    wsplitT_kernel<<<dim3(64, 64),  tb32>>>(wq, DIM, DIM, wqh, wql);
    wsplitT_kernel<<<dim3(64, 64),  tb32>>>(wk, DIM, DIM, wkh, wkl);
    wsplitT_kernel<<<dim3(64, 64),  tb32>>>(wv, DIM, DIM, wvh, wvl);
    wsplitT_kernel<<<dim3(64, 64),  tb32>>>(wo, DIM, DIM, woh, wol);
    wsplitT_kernel<<<dim3(176, 64), tb32>>>(w1, DIM, HIDDEN, w1h, w1l);
    wsplitT_kernel<<<dim3(176, 64), tb32>>>(w3, DIM, HIDDEN, w3h, w3l);
    wsplitT_kernel<<<dim3(64, 176), tb32>>>(w2, HIDDEN, DIM, w2h, w2l);

    // 1) xn = rmsnorm(x) -> split
    rmsnorm_split_kernel<<<S_LEN, 256>>>(x, ga, xnh, xnl);

    // 2) QKV (fp32 out)
    mma_gemm<0, 0><<<dim3(16, 16), 256, GEMM_SMEM>>>(xnh, xnl, DIM, 0, wqh, wql, DIM, 0,
        qf, nullptr, nullptr, nullptr, DIM, 0, DIM);
    mma_gemm<0, 0><<<dim3(16, 16), 256, GEMM_SMEM>>>(xnh, xnl, DIM, 0, wkh, wkl, DIM, 0,
        kf, nullptr, nullptr, nullptr, DIM, 0, DIM);
    mma_gemm<0, 0><<<dim3(16, 16), 256, GEMM_SMEM>>>(xnh, xnl, DIM, 0, wvh, wvl, DIM, 0,
        vf, nullptr, nullptr, nullptr, DIM, 0, DIM);

    // 3) RoPE + split q,k ; transpose+split v
    rope_split_kernel<<<(S_LEN * NHEAD * (HD / 2) + 255) / 256, 256>>>(qf, kf, fc, fs, qh, ql, kh, kl);
    vsplitT_kernel<<<dim3(64, 4, NHEAD), tb32>>>(vf, vTh, vTl);

    // 4) scores = Q @ K^T (per head, causal tile skip), fp32
    mma_gemm<0, 1><<<dim3(16, 16, NHEAD), 256, GEMM_SMEM>>>(qh, ql, DIM, HD, kh, kl, DIM, HD,
        sc, nullptr, nullptr, nullptr, S_LEN, (long long)S_LEN * S_LEN, HD);

    // 5) softmax -> split probs
    softmax_split_kernel<<<dim3(S_LEN, NHEAD), 256>>>(sc, pph, ppl);

    // 6) attn = P @ V (K truncated at causal boundary), split out
    mma_gemm<3, 2><<<dim3(1, 16, NHEAD), 256, GEMM_SMEM>>>(pph, ppl, S_LEN, (long long)S_LEN * S_LEN,
        vTh, vTl, S_LEN, (long long)HD * S_LEN,
        nullptr, nullptr, ath, atl, DIM, HD, S_LEN);

    // 7) h = x + attn @ wo (fp32)
    mma_gemm<1, 0><<<dim3(16, 16), 256, GEMM_SMEM>>>(ath, atl, DIM, 0, woh, wol, DIM, 0,
        h, x, nullptr, nullptr, DIM, 0, DIM);

    // 8) hn = rmsnorm(h) -> split
    rmsnorm_split_kernel<<<S_LEN, 256>>>(h, gf, hnh, hnl);

    // 9) u1a = hn @ w1 (fp32); u1 = silu(u1a) * (hn @ w3) -> split
    mma_gemm<0, 0><<<dim3(44, 16), 256, GEMM_SMEM>>>(hnh, hnl, DIM, 0, w1h, w1l, DIM, 0,
        u1a, nullptr, nullptr, nullptr, HIDDEN, 0, DIM);
    mma_gemm<2, 0><<<dim3(44, 16), 256, GEMM_SMEM>>>(hnh, hnl, DIM, 0, w3h, w3l, DIM, 0,
        nullptr, u1a, u1h, u1l, HIDDEN, 0, DIM);

    // 10) out = h + u1 @ w2 (fp32)
    mma_gemm<1, 0><<<dim3(16, 16), 256, GEMM_SMEM>>>(u1h, u1l, HIDDEN, 0, w2h, w2l, HIDDEN, 0,
        out, h, nullptr, nullptr, DIM, 0, HIDDEN);
}

// round 4
// speedup vs baseline: 5.4168x; 2.5045x over previous
#include <cuda_runtime.h>
#include <cuda_fp16.h>
#include <math.h>
#include <stdint.h>

#define S_LEN   2048
#define DIM     2048
#define NHEAD   16
#define HD      128
#define HIDDEN  5632
#define EPS     1e-6f

using fp16 = __half;

// ---------------------------------------------------------------------------
// Device scratch (no runtime allocation allowed)
// ---------------------------------------------------------------------------
__device__ float g_sc [(size_t)NHEAD * S_LEN * S_LEN];     // fp32 scores
__device__ float g_qf [S_LEN * DIM];
__device__ float g_kf [S_LEN * DIM];
__device__ float g_vf [S_LEN * DIM];
__device__ float g_h  [S_LEN * DIM];
__device__ float g_u1a[(size_t)S_LEN * HIDDEN];

__device__ fp16 g_xn [S_LEN * DIM];
__device__ fp16 g_q  [S_LEN * DIM];
__device__ fp16 g_k  [S_LEN * DIM];
__device__ fp16 g_vT [NHEAD * HD * S_LEN];
__device__ fp16 g_p  [(size_t)NHEAD * S_LEN * S_LEN];
__device__ fp16 g_at [S_LEN * DIM];
__device__ fp16 g_hn [S_LEN * DIM];
__device__ fp16 g_u1 [(size_t)S_LEN * HIDDEN];

__device__ fp16 g_wqT[DIM * DIM];
__device__ fp16 g_wkT[DIM * DIM];
__device__ fp16 g_wvT[DIM * DIM];
__device__ fp16 g_woT[DIM * DIM];
__device__ fp16 g_w1T[(size_t)HIDDEN * DIM];
__device__ fp16 g_w3T[(size_t)HIDDEN * DIM];
__device__ fp16 g_w2T[(size_t)DIM * HIDDEN];

// ---------------------------------------------------------------------------
// Helpers
// ---------------------------------------------------------------------------
__device__ __forceinline__ uint32_t smem_u32(const void* p) {
    uint32_t a;
    asm("{ .reg .u64 t; cvta.to.shared.u64 t, %1; cvt.u32.u64 %0, t; }" : "=r"(a) : "l"(p));
    return a;
}
__device__ __forceinline__ void cpa16(uint32_t d, const void* g) {
    asm volatile("cp.async.cg.shared.global [%0], [%1], 16;" :: "r"(d), "l"(g));
}
__device__ __forceinline__ void ldm_x4(uint32_t a, uint32_t (&f)[4]) {
    asm volatile("ldmatrix.sync.aligned.m8n8.x4.shared.b16 {%0,%1,%2,%3}, [%4];"
                 : "=r"(f[0]), "=r"(f[1]), "=r"(f[2]), "=r"(f[3]) : "r"(a));
}
__device__ __forceinline__ void mma16816(float (&c)[4], const uint32_t (&a)[4],
                                         uint32_t b0, uint32_t b1) {
    asm volatile("mma.sync.aligned.m16n8k16.row.col.f32.f16.f16.f32 "
                 "{%0,%1,%2,%3}, {%4,%5,%6,%7}, {%8,%9}, {%0,%1,%2,%3};"
                 : "+f"(c[0]), "+f"(c[1]), "+f"(c[2]), "+f"(c[3])
                 : "r"(a[0]), "r"(a[1]), "r"(a[2]), "r"(a[3]), "r"(b0), "r"(b1));
}

// swizzled byte offset within a 128x32-fp16 tile (64B rows, 16B segs)
__device__ __forceinline__ uint32_t swz(int row, int seg) {
    return (uint32_t)(row * 64 + ((seg ^ ((row >> 1) & 3)) << 4));
}

// stage a 128x32 fp16 tile smem<-gmem via cp.async (256 threads, 2 ops/thread)
__device__ __forceinline__ void load_tile(const fp16* __restrict__ src, int ld,
                                          uint32_t dst, int tid) {
#pragma unroll
    for (int i = 0; i < 2; i++) {
        const int s = tid + i * 256;        // 0..511
        const int row = s >> 2, seg = s & 3;
        cpa16(dst + swz(row, seg), src + (size_t)row * ld + seg * 8);
    }
}

// ---------------------------------------------------------------------------
// mma_gemm: C[M,N] = A[M,K] @ B[N,K]^T, fp16 operands, fp32 accum.
// EPI: 0 fp32; 1 fp32 + Dx; 2 fp16(silu(Dx)*acc); 3 fp16(acc)
// CAUSAL: 0 none; 1 skip bx>by; 2 K-loop ends at (by+1)*128
// 128x128 tile, 8 warps (2x4), warp 64x32, K-chunk 32, 3-stage cp.async.
// ---------------------------------------------------------------------------
#define NSTAGE 3
#define GEMM_SMEM (NSTAGE * 16384)

template<int EPI, int CAUSAL>
__global__ __launch_bounds__(256)
void mma_gemm(const fp16* __restrict__ A_, int lda, long long zA,
              const fp16* __restrict__ B_, int ldb, long long zB,
              float* __restrict__ Cf, const float* __restrict__ Dx,
              fp16* __restrict__ Ch, int ldc, long long zC, int K)
{
    const int bx = blockIdx.x, by = blockIdx.y, z = blockIdx.z;
    if (CAUSAL == 1 && bx > by) return;
    const int m0 = by * 128, n0 = bx * 128;
    int kEnd = K;
    if (CAUSAL == 2) { int ke = (by + 1) * 128; kEnd = ke < K ? ke : K; }
    const int nc = kEnd >> 5;

    extern __shared__ char smem[];
    const uint32_t sb = smem_u32(smem);
    const int tid = threadIdx.x, wid = tid >> 5, lid = tid & 31;
    const int wm = wid >> 2, wn = wid & 3;

    const fp16* pA = A_ + (size_t)z * zA + (size_t)m0 * lda;
    const fp16* pB = B_ + (size_t)z * zB + (size_t)n0 * ldb;

    float acc[4][4][4];
#pragma unroll
    for (int i = 0; i < 4; i++)
#pragma unroll
        for (int j = 0; j < 4; j++)
#pragma unroll
            for (int t = 0; t < 4; t++) acc[i][j][t] = 0.f;

    // prologue: stages 0..NSTAGE-2
#pragma unroll
    for (int s = 0; s < NSTAGE - 1; s++) {
        if (s < nc) {
            const uint32_t base = sb + s * 16384;
            load_tile(pA + s * 32, lda, base,        tid);
            load_tile(pB + s * 32, ldb, base + 8192, tid);
        }
        asm volatile("cp.async.commit_group;" ::: "memory");
    }

    const int quad = lid >> 3, rr = lid & 7;

    for (int c = 0; c < nc; c++) {
        const int cp = c + NSTAGE - 1;
        if (cp < nc) {
            const uint32_t base = sb + (cp % NSTAGE) * 16384;
            load_tile(pA + cp * 32, lda, base,        tid);
            load_tile(pB + cp * 32, ldb, base + 8192, tid);
        }
        asm volatile("cp.async.commit_group;" ::: "memory");
        asm volatile("cp.async.wait_group %0;" :: "n"(NSTAGE - 1) : "memory");
        __syncthreads();

        const uint32_t base = sb + (c % NSTAGE) * 16384;
#pragma unroll
        for (int ks = 0; ks < 2; ks++) {
            uint32_t AF[4][4], BF[2][4];
#pragma unroll
            for (int mi = 0; mi < 4; mi++) {
                const int row = wm * 64 + mi * 16 + ((quad & 1) << 3) + rr;
                const int seg = ks * 2 + (quad >> 1);
                ldm_x4(base + swz(row, seg), AF[mi]);
            }
#pragma unroll
            for (int nj = 0; nj < 2; nj++) {
                const int row = wn * 32 + nj * 16 + ((quad >> 1) << 3) + rr;
                const int seg = ks * 2 + (quad & 1);
                ldm_x4(base + 8192 + swz(row, seg), BF[nj]);
            }
#pragma unroll
            for (int mi = 0; mi < 4; mi++)
#pragma unroll
                for (int nj = 0; nj < 2; nj++) {
                    mma16816(acc[mi][nj * 2],     AF[mi], BF[nj][0], BF[nj][1]);
                    mma16816(acc[mi][nj * 2 + 1], AF[mi], BF[nj][2], BF[nj][3]);
                }
        }
        __syncthreads();
    }

    // epilogue (direct from registers)
    const int gid = lid >> 2, tig = lid & 3;
    if (Cf) Cf += (size_t)z * zC;
    if (Ch) Ch += (size_t)z * zC;

#pragma unroll
    for (int mi = 0; mi < 4; mi++) {
#pragma unroll
        for (int k4 = 0; k4 < 4; k4++) {
            const int col = n0 + wn * 32 + k4 * 8 + tig * 2;
#pragma unroll
            for (int h2 = 0; h2 < 2; h2++) {
                const int row = m0 + wm * 64 + mi * 16 + gid + h2 * 8;
                float v0 = acc[mi][k4][h2 * 2 + 0];
                float v1 = acc[mi][k4][h2 * 2 + 1];
                const size_t off = (size_t)row * ldc + col;
                if (EPI == 0) {
                    *(float2*)(Cf + off) = make_float2(v0, v1);
                } else if (EPI == 1) {
                    float2 d = *(const float2*)(Dx + off);
                    *(float2*)(Cf + off) = make_float2(v0 + d.x, v1 + d.y);
                } else {
                    if (EPI == 2) {
                        float2 d = *(const float2*)(Dx + off);
                        v0 *= d.x / (1.f + expf(-d.x));
                        v1 *= d.y / (1.f + expf(-d.y));
                    }
                    __half2 t;
                    t.x = __float2half(v0); t.y = __float2half(v1);
                    *(__half2*)(Ch + off) = t;
                }
            }
        }
    }
}

// ---------------------------------------------------------------------------
// RMSNorm -> fp16
// ---------------------------------------------------------------------------
__global__ void rmsnorm_h_kernel(const float* __restrict__ x, const float* __restrict__ g,
                                 fp16* __restrict__ y) {
    const int row = blockIdx.x;
    const float* xr = x + (size_t)row * DIM;
    float ss = 0.f;
    for (int i = threadIdx.x; i < DIM / 4; i += 256) {
        float4 v = ((const float4*)xr)[i];
        ss += v.x * v.x + v.y * v.y + v.z * v.z + v.w * v.w;
    }
    __shared__ float red[8];
    __shared__ float rr_s;
#pragma unroll
    for (int o = 16; o; o >>= 1) ss += __shfl_xor_sync(0xffffffffu, ss, o);
    if ((threadIdx.x & 31) == 0) red[threadIdx.x >> 5] = ss;
    __syncthreads();
    if (threadIdx.x == 0) {
        float v = 0.f;
#pragma unroll
        for (int i = 0; i < 8; i++) v += red[i];
        rr_s = rsqrtf(v * (1.0f / DIM) + EPS);
    }
    __syncthreads();
    const float rr = rr_s;
    for (int i = threadIdx.x; i < DIM / 4; i += 256) {
        float4 v  = ((const float4*)xr)[i];
        float4 gg = ((const float4*)g)[i];
        __half2 a, b;
        a.x = __float2half(v.x * rr * gg.x);
        a.y = __float2half(v.y * rr * gg.y);
        b.x = __float2half(v.z * rr * gg.z);
        b.y = __float2half(v.w * rr * gg.w);
        const size_t o = (size_t)row * DIM + i * 4;
        *(__half2*)(y + o)     = a;
        *(__half2*)(y + o + 2) = b;
    }
}

// ---------------------------------------------------------------------------
// Weight transpose + convert: W[K,N] -> WT[N,K] fp16
// ---------------------------------------------------------------------------
__global__ void wconvT_kernel(const float* __restrict__ W, int K, int N,
                              fp16* __restrict__ T) {
    __shared__ float tb[32][33];
    const int n0 = blockIdx.x * 32, k0 = blockIdx.y * 32;
    const int tx = threadIdx.x, ty = threadIdx.y;
#pragma unroll
    for (int r = 0; r < 4; r++)
        tb[ty + 8 * r][tx] = W[(size_t)(k0 + ty + 8 * r) * N + n0 + tx];
    __syncthreads();
#pragma unroll
    for (int r = 0; r < 4; r++)
        T[(size_t)(n0 + ty + 8 * r) * K + k0 + tx] = __float2half(tb[tx][ty + 8 * r]);
}

// V transpose per head + convert: v[S,DIM] -> vT[h][d][t] fp16
__global__ void vconvT_kernel(const float* __restrict__ vf, fp16* __restrict__ T) {
    __shared__ float tb[32][33];
    const int t0 = blockIdx.x * 32, d0 = blockIdx.y * 32, h = blockIdx.z;
    const int tx = threadIdx.x, ty = threadIdx.y;
#pragma unroll
    for (int r = 0; r < 4; r++)
        tb[ty + 8 * r][tx] = vf[(size_t)(t0 + ty + 8 * r) * DIM + h * HD + d0 + tx];
    __syncthreads();
#pragma unroll
    for (int r = 0; r < 4; r++)
        T[((size_t)h * HD + d0 + ty + 8 * r) * S_LEN + t0 + tx] = __float2half(tb[tx][ty + 8 * r]);
}

// ---------------------------------------------------------------------------
// RoPE on fp32 q,k -> fp16
// ---------------------------------------------------------------------------
__global__ void rope_h_kernel(const float* __restrict__ qf, const float* __restrict__ kf,
                              const float* __restrict__ fc, const float* __restrict__ fs,
                              fp16* __restrict__ qo, fp16* __restrict__ ko) {
    const int idx = blockIdx.x * blockDim.x + threadIdx.x;
    if (idx >= S_LEN * NHEAD * (HD / 2)) return;
    const int i = idx & 63;
    const int h = (idx >> 6) & 15;
    const int s = idx >> 10;
    const float c  = fc[s * 64 + i];
    const float sn = fs[s * 64 + i];
    const size_t off = (size_t)s * DIM + h * HD + 2 * i;
    {
        float qr = qf[off], qi = qf[off + 1];
        __half2 t;
        t.x = __float2half(qr * c - qi * sn);
        t.y = __float2half(qr * sn + qi * c);
        *(__half2*)(qo + off) = t;
    }
    {
        float kr = kf[off], ki = kf[off + 1];
        __half2 t;
        t.x = __float2half(kr * c - ki * sn);
        t.y = __float2half(kr * sn + ki * c);
        *(__half2*)(ko + off) = t;
    }
}

// ---------------------------------------------------------------------------
// Causal softmax on fp32 scores -> fp16 probs (zeros only up to causal tile pad)
// ---------------------------------------------------------------------------
__global__ void softmax_h_kernel(const float* __restrict__ sc, fp16* __restrict__ p) {
    const int s = blockIdx.x, h = blockIdx.y;
    const float* row = sc + ((size_t)h * S_LEN + s) * S_LEN;
    fp16* orow = p + ((size_t)h * S_LEN + s) * S_LEN;
    const int L = s + 1;
    const int Lpad = ((s >> 7) + 1) << 7;      // PV only reads t < Lpad
    const float scale = 0.08838834764831845f;

    __shared__ float red[8];
    __shared__ float bmax, binv;

    float m = -1e30f;
    for (int t = threadIdx.x; t < L; t += 256) m = fmaxf(m, row[t]);
#pragma unroll
    for (int o = 16; o; o >>= 1) m = fmaxf(m, __shfl_xor_sync(0xffffffffu, m, o));
    if ((threadIdx.x & 31) == 0) red[threadIdx.x >> 5] = m;
    __syncthreads();
    if (threadIdx.x == 0) {
        float v = red[0];
#pragma unroll
        for (int i = 1; i < 8; i++) v = fmaxf(v, red[i]);
        bmax = v * scale;
    }
    __syncthreads();
    const float mm = bmax;

    float sum = 0.f;
    for (int t = threadIdx.x; t < L; t += 256) sum += expf(row[t] * scale - mm);
#pragma unroll
    for (int o = 16; o; o >>= 1) sum += __shfl_xor_sync(0xffffffffu, sum, o);
    if ((threadIdx.x & 31) == 0) red[threadIdx.x >> 5] = sum;
    __syncthreads();
    if (threadIdx.x == 0) {
        float v = 0.f;
#pragma unroll
        for (int i = 0; i < 8; i++) v += red[i];
        binv = 1.f / v;
    }
    __syncthreads();
    const float inv = binv;

    for (int t = threadIdx.x; t < Lpad; t += 256) {
        float e = (t < L) ? expf(row[t] * scale - mm) * inv : 0.f;
        orow[t] = __float2half(e);
    }
}

// ---------------------------------------------------------------------------
// Orchestration
// ---------------------------------------------------------------------------
extern "C" void kernel_launch(void* const* d_in, const int* in_sizes, int n_in,
                              void* d_out, int out_size) {
    const float* x  = (const float*)d_in[0];
    const float* fc = (const float*)d_in[1];
    const float* fs = (const float*)d_in[2];
    const float* wq = (const float*)d_in[4];
    const float* wk = (const float*)d_in[5];
    const float* wv = (const float*)d_in[6];
    const float* wo = (const float*)d_in[7];
    const float* w1 = (const float*)d_in[8];
    const float* w2 = (const float*)d_in[9];
    const float* w3 = (const float*)d_in[10];
    const float* ga = (const float*)d_in[11];
    const float* gf = (const float*)d_in[12];
    float* out = (float*)d_out;

    cudaFuncSetAttribute(mma_gemm<0, 0>, cudaFuncAttributeMaxDynamicSharedMemorySize, GEMM_SMEM);
    cudaFuncSetAttribute(mma_gemm<0, 1>, cudaFuncAttributeMaxDynamicSharedMemorySize, GEMM_SMEM);
    cudaFuncSetAttribute(mma_gemm<3, 2>, cudaFuncAttributeMaxDynamicSharedMemorySize, GEMM_SMEM);
    cudaFuncSetAttribute(mma_gemm<1, 0>, cudaFuncAttributeMaxDynamicSharedMemorySize, GEMM_SMEM);
    cudaFuncSetAttribute(mma_gemm<2, 0>, cudaFuncAttributeMaxDynamicSharedMemorySize, GEMM_SMEM);

    float *sc, *qf, *kf, *vf, *h, *u1a;
    fp16 *xn, *q, *k, *vT, *p, *at, *hn, *u1;
    fp16 *wqT, *wkT, *wvT, *woT, *w1T, *w2T, *w3T;
    cudaGetSymbolAddress((void**)&sc,  g_sc);
    cudaGetSymbolAddress((void**)&qf,  g_qf);
    cudaGetSymbolAddress((void**)&kf,  g_kf);
    cudaGetSymbolAddress((void**)&vf,  g_vf);
    cudaGetSymbolAddress((void**)&h,   g_h);
    cudaGetSymbolAddress((void**)&u1a, g_u1a);
    cudaGetSymbolAddress((void**)&xn,  g_xn);
    cudaGetSymbolAddress((void**)&q,   g_q);
    cudaGetSymbolAddress((void**)&k,   g_k);
    cudaGetSymbolAddress((void**)&vT,  g_vT);
    cudaGetSymbolAddress((void**)&p,   g_p);
    cudaGetSymbolAddress((void**)&at,  g_at);
    cudaGetSymbolAddress((void**)&hn,  g_hn);
    cudaGetSymbolAddress((void**)&u1,  g_u1);
    cudaGetSymbolAddress((void**)&wqT, g_wqT);
    cudaGetSymbolAddress((void**)&wkT, g_wkT);
    cudaGetSymbolAddress((void**)&wvT, g_wvT);
    cudaGetSymbolAddress((void**)&woT, g_woT);
    cudaGetSymbolAddress((void**)&w1T, g_w1T);
    cudaGetSymbolAddress((void**)&w2T, g_w2T);
    cudaGetSymbolAddress((void**)&w3T, g_w3T);

    const dim3 tb32(32, 8);

    // Weight transpose + convert
    wconvT_kernel<<<dim3(64, 64),  tb32>>>(wq, DIM, DIM, wqT);
    wconvT_kernel<<<dim3(64, 64),  tb32>>>(wk, DIM, DIM, wkT);
    wconvT_kernel<<<dim3(64, 64),  tb32>>>(wv, DIM, DIM, wvT);
    wconvT_kernel<<<dim3(64, 64),  tb32>>>(wo, DIM, DIM, woT);
    wconvT_kernel<<<dim3(176, 64), tb32>>>(w1, DIM, HIDDEN, w1T);
    wconvT_kernel<<<dim3(176, 64), tb32>>>(w3, DIM, HIDDEN, w3T);
    wconvT_kernel<<<dim3(64, 176), tb32>>>(w2, HIDDEN, DIM, w2T);

    // 1) xn = rmsnorm(x) fp16
    rmsnorm_h_kernel<<<S_LEN, 256>>>(x, ga, xn);

    // 2) QKV (fp32 out for rope / v transpose)
    mma_gemm<0, 0><<<dim3(16, 16), 256, GEMM_SMEM>>>(xn, DIM, 0, wqT, DIM, 0,
        qf, nullptr, nullptr, DIM, 0, DIM);
    mma_gemm<0, 0><<<dim3(16, 16), 256, GEMM_SMEM>>>(xn, DIM, 0, wkT, DIM, 0,
        kf, nullptr, nullptr, DIM, 0, DIM);
    mma_gemm<0, 0><<<dim3(16, 16), 256, GEMM_SMEM>>>(xn, DIM, 0, wvT, DIM, 0,
        vf, nullptr, nullptr, DIM, 0, DIM);

    // 3) RoPE -> fp16 q,k ; transpose+convert v
    rope_h_kernel<<<(S_LEN * NHEAD * (HD / 2) + 255) / 256, 256>>>(qf, kf, fc, fs, q, k);
    vconvT_kernel<<<dim3(64, 4, NHEAD), tb32>>>(vf, vT);

    // 4) scores = Q @ K^T (per head, causal tile skip), fp32
    mma_gemm<0, 1><<<dim3(16, 16, NHEAD), 256, GEMM_SMEM>>>(q, DIM, HD, k, DIM, HD,
        sc, nullptr, nullptr, S_LEN, (long long)S_LEN * S_LEN, HD);

    // 5) softmax -> fp16 probs
    softmax_h_kernel<<<dim3(S_LEN, NHEAD), 256>>>(sc, p);

    // 6) attn = P @ V (K truncated at causal boundary), fp16 out
    mma_gemm<3, 2><<<dim3(1, 16, NHEAD), 256, GEMM_SMEM>>>(p, S_LEN, (long long)S_LEN * S_LEN,
        vT, S_LEN, (long long)HD * S_LEN,
        nullptr, nullptr, at, DIM, HD, S_LEN);

    // 7) h = x + attn @ wo (fp32)
    mma_gemm<1, 0><<<dim3(16, 16), 256, GEMM_SMEM>>>(at, DIM, 0, woT, DIM, 0,
        h, x, nullptr, DIM, 0, DIM);

    // 8) hn = rmsnorm(h) fp16
    rmsnorm_h_kernel<<<S_LEN, 256>>>(h, gf, hn);

    // 9) u1a = hn @ w1 (fp32); u1 = silu(u1a) * (hn @ w3) fp16
    mma_gemm<0, 0><<<dim3(44, 16), 256, GEMM_SMEM>>>(hn, DIM, 0, w1T, DIM, 0,
        u1a, nullptr, nullptr, HIDDEN, 0, DIM);
    mma_gemm<2, 0><<<dim3(44, 16), 256, GEMM_SMEM>>>(hn, DIM, 0, w3T, DIM, 0,
        nullptr, u1a, u1, HIDDEN, 0, DIM);

    // 10) out = h + u1 @ w2 (fp32)
    mma_gemm<1, 0><<<dim3(16, 16), 256, GEMM_SMEM>>>(u1, HIDDEN, 0, w2T, HIDDEN, 0,
        out, h, nullptr, DIM, 0, HIDDEN);
}